// round 6
// baseline (speedup 1.0000x reference)
#include <cuda_runtime.h>
#include <cuda_bf16.h>
#include <cstdint>

// Problem constants: B=8,H=64,Wd=128 -> NROWS=65536, D=272, NC=19, P=524288, NI=4096
#define D_FEAT    272
#define NC_OUT    19
#define NC_PAD    20          // padded outputs (10 f32x2 pairs)
#define NROWS_MAX 65536

// ---- scratch ----
__device__ __align__(16) float g_proj[NROWS_MAX * NC_PAD];   // 5.24 MB (L2-resident)

__device__ __forceinline__ void ffma2(unsigned long long& d,
                                      unsigned long long a,
                                      unsigned long long b) {
    asm("fma.rn.f32x2 %0, %1, %2, %0;" : "+l"(d) : "l"(a), "l"(b));
}

// ============================================================
// Kernel 1: projection GEMM  proj[r][o] = sum_c feats[r][c]*W[c][o]
// 128 threads, 256 rows/block, 2 rows/thread, k-chunks of 16.
// x staged PRE-DUPLICATED as f32x2 in smem (1 LDS.64 per use);
// W pairs loaded via ld.shared.v2.b64 (5 loads per k).
// ============================================================
#define P1_THREADS 128
#define P1_ROWS    256
#define KCHUNK     16
#define XS_STRIDE  17          // ull stride: 2-way max conflict on LDS.64

__global__ __launch_bounds__(P1_THREADS)
void proj_gemm_kernel(const float4* __restrict__ feats4,   // [NROWS, 68]
                      const float*  __restrict__ Wmat,     // [272, 19]
                      int nrows)
{
    __shared__ float wsh[D_FEAT * NC_PAD];                         // 21.8 KB
    __shared__ unsigned long long xs2[P1_ROWS * XS_STRIDE];        // 34.8 KB

    const int tid = threadIdx.x;
    const int rowBase = blockIdx.x * P1_ROWS;

    // stage W (pad col 19 with zeros)
    for (int i = tid; i < D_FEAT * NC_PAD; i += P1_THREADS) {
        const int c = i / NC_PAD, o = i % NC_PAD;
        wsh[i] = (o < NC_OUT) ? Wmat[c * NC_OUT + o] : 0.0f;
    }

    const uint32_t wbase = (uint32_t)__cvta_generic_to_shared(wsh);
    const uint32_t xbase = (uint32_t)__cvta_generic_to_shared(xs2);

    const int r0 = rowBase + tid;
    const int r1 = rowBase + tid + P1_THREADS;
    const bool v0 = r0 < nrows, v1 = r1 < nrows;

    unsigned long long acc0[NC_PAD / 2], acc1[NC_PAD / 2];
    #pragma unroll
    for (int j = 0; j < NC_PAD / 2; ++j) { acc0[j] = 0ull; acc1[j] = 0ull; }

    for (int cc = 0; cc < D_FEAT; cc += KCHUNK) {
        __syncthreads();
        // stage 256 rows x 16 channels, duplicated into f32x2 pairs
        #pragma unroll
        for (int j = tid; j < P1_ROWS * 4; j += P1_THREADS) {
            const int rr = j >> 2;
            const int qq = j & 3;
            const int gr = rowBase + rr;
            float4 val = make_float4(0.f, 0.f, 0.f, 0.f);
            if (gr < nrows) val = __ldg(&feats4[(long)gr * 68 + (cc >> 2) + qq]);
            unsigned long long* dst = &xs2[rr * XS_STRIDE + qq * 4];
            unsigned long long p0, p1, p2, p3;
            asm("mov.b64 %0, {%1, %1};" : "=l"(p0) : "f"(val.x));
            asm("mov.b64 %0, {%1, %1};" : "=l"(p1) : "f"(val.y));
            asm("mov.b64 %0, {%1, %1};" : "=l"(p2) : "f"(val.z));
            asm("mov.b64 %0, {%1, %1};" : "=l"(p3) : "f"(val.w));
            dst[0] = p0; dst[1] = p1; dst[2] = p2; dst[3] = p3;
        }
        __syncthreads();

        #pragma unroll
        for (int k = 0; k < KCHUNK; ++k) {
            const int c = cc + k;
            // duplicated x values: single LDS.64 each
            unsigned long long x0p, x1p;
            {
                const uint32_t a0 = xbase + (tid * XS_STRIDE + k) * 8u;
                const uint32_t a1 = xbase + ((tid + P1_THREADS) * XS_STRIDE + k) * 8u;
                asm("ld.shared.b64 %0, [%1];" : "=l"(x0p) : "r"(a0));
                asm("ld.shared.b64 %0, [%1];" : "=l"(x1p) : "r"(a1));
            }
            // W row: 10 pairs via 5x ld.shared.v2.b64 (warp-uniform -> broadcast)
            unsigned long long w[10];
            const uint32_t wa = wbase + (uint32_t)c * (NC_PAD * 4u);
            asm("ld.shared.v2.b64 {%0,%1}, [%2];"      : "=l"(w[0]), "=l"(w[1]) : "r"(wa));
            asm("ld.shared.v2.b64 {%0,%1}, [%2+16];"   : "=l"(w[2]), "=l"(w[3]) : "r"(wa));
            asm("ld.shared.v2.b64 {%0,%1}, [%2+32];"   : "=l"(w[4]), "=l"(w[5]) : "r"(wa));
            asm("ld.shared.v2.b64 {%0,%1}, [%2+48];"   : "=l"(w[6]), "=l"(w[7]) : "r"(wa));
            asm("ld.shared.v2.b64 {%0,%1}, [%2+64];"   : "=l"(w[8]), "=l"(w[9]) : "r"(wa));
            #pragma unroll
            for (int j = 0; j < NC_PAD / 2; ++j) {
                ffma2(acc0[j], x0p, w[j]);
                ffma2(acc1[j], x1p, w[j]);
            }
        }
    }

    unsigned long long* proj8 = reinterpret_cast<unsigned long long*>(g_proj);
    if (v0) {
        #pragma unroll
        for (int j = 0; j < NC_PAD / 2; ++j)
            proj8[(long)r0 * (NC_PAD / 2) + j] = acc0[j];
    }
    if (v1) {
        #pragma unroll
        for (int j = 0; j < NC_PAD / 2; ++j)
            proj8[(long)r1 * (NC_PAD / 2) + j] = acc1[j];
    }
}

// ============================================================
// Kernel 2: gather projected rows, segment-mean, +bias, sigmoid
// one block (128 threads) per segment; range via binary search
// ============================================================
#define P2_THREADS 128

__global__ __launch_bounds__(P2_THREADS)
void pool_head_kernel(const int* __restrict__ point_idx,
                      const int* __restrict__ seg_ids,   // sorted
                      int P,
                      const float* __restrict__ bias,
                      float* __restrict__ out)           // [NI, 19]
{
    const int s   = blockIdx.x;
    const int tid = threadIdx.x;

    __shared__ int sh_range[2];
    if (tid < 2) {
        const int target = s + tid;       // lower_bound(s), lower_bound(s+1)
        int lo = 0, hi = P;
        while (lo < hi) {
            int mid = (lo + hi) >> 1;
            if (__ldg(&seg_ids[mid]) < target) lo = mid + 1; else hi = mid;
        }
        sh_range[tid] = lo;
    }
    __syncthreads();
    const int start = sh_range[0];
    const int end   = sh_range[1];

    const float4* proj4 = reinterpret_cast<const float4*>(g_proj);

    float4 a0 = make_float4(0.f,0.f,0.f,0.f);
    float4 a1 = a0, a2 = a0, a3 = a0, a4 = a0;

    for (int i = start + tid; i < end; i += P2_THREADS) {
        const long r = point_idx[i];
        const float4* row = proj4 + r * 5;
        const float4 v0 = __ldg(row + 0);
        const float4 v1 = __ldg(row + 1);
        const float4 v2 = __ldg(row + 2);
        const float4 v3 = __ldg(row + 3);
        const float4 v4 = __ldg(row + 4);
        a0.x += v0.x; a0.y += v0.y; a0.z += v0.z; a0.w += v0.w;
        a1.x += v1.x; a1.y += v1.y; a1.z += v1.z; a1.w += v1.w;
        a2.x += v2.x; a2.y += v2.y; a2.z += v2.z; a2.w += v2.w;
        a3.x += v3.x; a3.y += v3.y; a3.z += v3.z; a3.w += v3.w;
        a4.x += v4.x; a4.y += v4.y; a4.z += v4.z; a4.w += v4.w;
    }

    float vals[20] = { a0.x,a0.y,a0.z,a0.w, a1.x,a1.y,a1.z,a1.w,
                       a2.x,a2.y,a2.z,a2.w, a3.x,a3.y,a3.z,a3.w,
                       a4.x,a4.y,a4.z,a4.w };
    #pragma unroll
    for (int d = 16; d; d >>= 1) {
        #pragma unroll
        for (int j = 0; j < 20; ++j)
            vals[j] += __shfl_xor_sync(0xFFFFFFFFu, vals[j], d);
    }

    __shared__ float red[P2_THREADS / 32][20];
    const int warp = tid >> 5, lane = tid & 31;
    if (lane == 0) {
        #pragma unroll
        for (int j = 0; j < 20; ++j) red[warp][j] = vals[j];
    }
    __syncthreads();

    if (tid < NC_OUT) {
        float v = red[0][tid] + red[1][tid] + red[2][tid] + red[3][tid];
        const float inv = 1.0f / (float)max(end - start, 1);
        const float o = v * inv + __ldg(&bias[tid]);
        out[s * NC_OUT + tid] = 1.0f / (1.0f + expf(-o));
    }
}

// ============================================================
extern "C" void kernel_launch(void* const* d_in, const int* in_sizes, int n_in,
                              void* d_out, int out_size)
{
    // order: class_capsules, W, b, point_idx, segment_ids, num_segments
    const float4* feats4    = (const float4*)d_in[0];
    const float*  Wmat      = (const float*) d_in[1];
    const float*  bias      = (const float*) d_in[2];
    const int*    point_idx = (const int*)   d_in[3];
    const int*    seg_ids   = (const int*)   d_in[4];
    const int     P         = in_sizes[3];
    const int     nrows     = in_sizes[0] / D_FEAT;
    const int     NI        = out_size / NC_OUT;
    float* out = (float*)d_out;

    proj_gemm_kernel<<<(nrows + P1_ROWS - 1) / P1_ROWS, P1_THREADS>>>(
        feats4, Wmat, nrows);

    pool_head_kernel<<<NI, P2_THREADS>>>(point_idx, seg_ids, P, bias, out);
}